// round 1
// baseline (speedup 1.0000x reference)
#include <cuda_runtime.h>
#include <cuda_bf16.h>
#include <cstdint>

// Problem constants
#define NN 100000
#define EE 1600000
#define FIN 256
#define FOUT 128      // H*D = 4*32
#define SCAN_CHUNK 256
#define NBLK_SCAN ((NN + SCAN_CHUNK - 1) / SCAN_CHUNK)   // 391

// ---------------- device scratch (static globals; no allocation) -------------
__device__ float4 g_ft4[(size_t)NN * 32];   // ft [N,128] viewed as float4x32 (51.2MB)
__device__ float4 g_el[NN];                 // el [N,4]
__device__ float4 g_er[NN];                 // er [N,4]
__device__ int    g_cnt[NN];
__device__ int    g_off[NN];
__device__ int    g_cur[NN];
__device__ int    g_srcs[EE];               // src ids sorted by dst
__device__ int    g_part[512];              // scan partials (NBLK_SCAN <= 512)

// ---------------- zero counts ------------------------------------------------
__global__ void k_zero_cnt() {
    int i = blockIdx.x * blockDim.x + threadIdx.x;
    if (i < NN) g_cnt[i] = 0;
}

// ---------------- GEMM: ft = feat @ W^T  (fp32, 128x128x8 tiles) -------------
__global__ __launch_bounds__(256) void k_gemm(const float* __restrict__ A,
                                              const float* __restrict__ W) {
    __shared__ float As[8][128];
    __shared__ float Bs[8][128];
    const int tid = threadIdx.x;
    const int tx = tid & 15;        // col group (8 cols each)
    const int ty = tid >> 4;        // row group (8 rows each)
    const int row0 = blockIdx.x * 128;

    const int lr = tid >> 1;        // 0..127 (tile row / W row)
    const int lq = (tid & 1) * 4;   // 0 or 4

    float acc[8][8];
#pragma unroll
    for (int i = 0; i < 8; i++)
#pragma unroll
        for (int j = 0; j < 8; j++) acc[i][j] = 0.f;

    for (int k0 = 0; k0 < FIN; k0 += 8) {
        // A tile: 128 rows x 8 k, transposed into As[k][row]
        int gr = row0 + lr;
        float4 a4 = make_float4(0.f, 0.f, 0.f, 0.f);
        if (gr < NN) a4 = *(const float4*)(A + (size_t)gr * FIN + k0 + lq);
        As[lq + 0][lr] = a4.x; As[lq + 1][lr] = a4.y;
        As[lq + 2][lr] = a4.z; As[lq + 3][lr] = a4.w;
        // W tile: 128 out-cols x 8 k, transposed into Bs[k][col]
        float4 b4 = *(const float4*)(W + (size_t)lr * FIN + k0 + lq);
        Bs[lq + 0][lr] = b4.x; Bs[lq + 1][lr] = b4.y;
        Bs[lq + 2][lr] = b4.z; Bs[lq + 3][lr] = b4.w;
        __syncthreads();

#pragma unroll
        for (int kk = 0; kk < 8; kk++) {
            float a[8], b[8];
#pragma unroll
            for (int i = 0; i < 8; i++) a[i] = As[kk][ty * 8 + i];
#pragma unroll
            for (int j = 0; j < 8; j++) b[j] = Bs[kk][tx * 8 + j];
#pragma unroll
            for (int i = 0; i < 8; i++)
#pragma unroll
                for (int j = 0; j < 8; j++) acc[i][j] = fmaf(a[i], b[j], acc[i][j]);
        }
        __syncthreads();
    }

    float* ft = (float*)g_ft4;
#pragma unroll
    for (int i = 0; i < 8; i++) {
        int gr = row0 + ty * 8 + i;
        if (gr < NN) {
            float4 v0 = make_float4(acc[i][0], acc[i][1], acc[i][2], acc[i][3]);
            float4 v1 = make_float4(acc[i][4], acc[i][5], acc[i][6], acc[i][7]);
            *(float4*)(ft + (size_t)gr * FOUT + tx * 8)     = v0;
            *(float4*)(ft + (size_t)gr * FOUT + tx * 8 + 4) = v1;
        }
    }
}

// ---------------- per-node attention logits el/er (warp per node) ------------
__global__ void k_elr(const float* __restrict__ al, const float* __restrict__ ar) {
    int gw = (blockIdx.x * blockDim.x + threadIdx.x) >> 5;
    int lane = threadIdx.x & 31;
    if (gw >= NN) return;
    const float* ft = (const float*)g_ft4 + (size_t)gw * FOUT;
    float el[4], er[4];
#pragma unroll
    for (int h = 0; h < 4; h++) {
        float f = ft[h * 32 + lane];
        el[h] = f * al[h * 32 + lane];
        er[h] = f * ar[h * 32 + lane];
    }
#pragma unroll
    for (int h = 0; h < 4; h++) {
#pragma unroll
        for (int o = 16; o > 0; o >>= 1) {
            el[h] += __shfl_xor_sync(0xFFFFFFFFu, el[h], o);
            er[h] += __shfl_xor_sync(0xFFFFFFFFu, er[h], o);
        }
    }
    if (lane == 0) {
        g_el[gw] = make_float4(el[0], el[1], el[2], el[3]);
        g_er[gw] = make_float4(er[0], er[1], er[2], er[3]);
    }
}

// ---------------- degree histogram -------------------------------------------
__global__ void k_hist(const int* __restrict__ dst) {
    int e = blockIdx.x * blockDim.x + threadIdx.x;
    if (e < EE) atomicAdd(&g_cnt[dst[e]], 1);
}

// ---------------- scan: block sums -------------------------------------------
__global__ void k_blocksum() {
    __shared__ int s[SCAN_CHUNK];
    int t = threadIdx.x;
    int i = blockIdx.x * SCAN_CHUNK + t;
    s[t] = (i < NN) ? g_cnt[i] : 0;
    __syncthreads();
#pragma unroll
    for (int o = SCAN_CHUNK / 2; o > 0; o >>= 1) {
        if (t < o) s[t] += s[t + o];
        __syncthreads();
    }
    if (t == 0) g_part[blockIdx.x] = s[0];
}

// ---------------- scan: exclusive scan of partials (one block) ---------------
__global__ void k_scanpart() {
    __shared__ int s[512];
    int t = threadIdx.x;
    s[t] = (t < NBLK_SCAN) ? g_part[t] : 0;
    __syncthreads();
    for (int o = 1; o < 512; o <<= 1) {
        int add = (t >= o) ? s[t - o] : 0;
        __syncthreads();
        s[t] += add;
        __syncthreads();
    }
    if (t < NBLK_SCAN) g_part[t] = (t == 0) ? 0 : s[t - 1];
}

// ---------------- scan: write offsets + cursors ------------------------------
__global__ void k_scanwrite() {
    __shared__ int s[SCAN_CHUNK];
    int t = threadIdx.x;
    int i = blockIdx.x * SCAN_CHUNK + t;
    s[t] = (i < NN) ? g_cnt[i] : 0;
    __syncthreads();
    for (int o = 1; o < SCAN_CHUNK; o <<= 1) {
        int add = (t >= o) ? s[t - o] : 0;
        __syncthreads();
        s[t] += add;
        __syncthreads();
    }
    int excl = (t == 0) ? 0 : s[t - 1];
    int base = g_part[blockIdx.x];
    if (i < NN) {
        g_off[i] = base + excl;
        g_cur[i] = base + excl;
    }
}

// ---------------- scatter edges by dst ---------------------------------------
__global__ void k_scatter(const int* __restrict__ src, const int* __restrict__ dst) {
    int e = blockIdx.x * blockDim.x + threadIdx.x;
    if (e >= EE) return;
    int d = dst[e];
    int pos = atomicAdd(&g_cur[d], 1);
    g_srcs[pos] = src[e];
}

// ---------------- aggregation: warp per dst node -----------------------------
__global__ void k_agg(float* __restrict__ out) {
    int gw = (blockIdx.x * blockDim.x + threadIdx.x) >> 5;
    int lane = threadIdx.x & 31;
    if (gw >= NN) return;

    const int start = g_off[gw];
    const int cnt = g_cnt[gw];
    const float4 er4 = g_er[gw];
    const float* ft = (const float*)g_ft4;

    float s0 = 0.f, s1 = 0.f, s2 = 0.f, s3 = 0.f;
    float a0 = 0.f, a1 = 0.f, a2 = 0.f, a3 = 0.f;

    for (int i = 0; i < cnt; i++) {
        int s = g_srcs[start + i];
        float4 el4 = g_el[s];
        float e0 = el4.x + er4.x; e0 = (e0 > 0.f) ? e0 : 0.2f * e0;
        float e1 = el4.y + er4.y; e1 = (e1 > 0.f) ? e1 : 0.2f * e1;
        float e2 = el4.z + er4.z; e2 = (e2 > 0.f) ? e2 : 0.2f * e2;
        float e3 = el4.w + er4.w; e3 = (e3 > 0.f) ? e3 : 0.2f * e3;
        float p0 = __expf(e0), p1 = __expf(e1), p2 = __expf(e2), p3 = __expf(e3);
        const float* fs = ft + (size_t)s * FOUT + lane;
        a0 = fmaf(p0, fs[0],  a0);
        a1 = fmaf(p1, fs[32], a1);
        a2 = fmaf(p2, fs[64], a2);
        a3 = fmaf(p3, fs[96], a3);
        s0 += p0; s1 += p1; s2 += p2; s3 += p3;
    }

    float* o = out + (size_t)gw * FOUT + lane;
    o[0]  = (s0 > 0.f) ? a0 / s0 : 0.f;
    o[32] = (s1 > 0.f) ? a1 / s1 : 0.f;
    o[64] = (s2 > 0.f) ? a2 / s2 : 0.f;
    o[96] = (s3 > 0.f) ? a3 / s3 : 0.f;
}

// ---------------- launch ------------------------------------------------------
extern "C" void kernel_launch(void* const* d_in, const int* in_sizes, int n_in,
                              void* d_out, int out_size) {
    const float* feat = (const float*)d_in[0];
    const float* fc_w = (const float*)d_in[1];
    const float* attn_l = (const float*)d_in[2];
    const float* attn_r = (const float*)d_in[3];
    const int* src = (const int*)d_in[4];
    const int* dst = (const int*)d_in[5];
    float* out = (float*)d_out;

    (void)in_sizes; (void)n_in; (void)out_size;

    k_zero_cnt<<<(NN + 511) / 512, 512>>>();
    k_gemm<<<(NN + 127) / 128, 256>>>(feat, fc_w);
    k_elr<<<(NN * 32 + 255) / 256, 256>>>(attn_l, attn_r);
    k_hist<<<(EE + 255) / 256, 256>>>(dst);
    k_blocksum<<<NBLK_SCAN, SCAN_CHUNK>>>();
    k_scanpart<<<1, 512>>>();
    k_scanwrite<<<NBLK_SCAN, SCAN_CHUNK>>>();
    k_scatter<<<(EE + 255) / 256, 256>>>(src, dst);
    k_agg<<<(NN * 32 + 255) / 256, 256>>>(out);
}

// round 3
// speedup vs baseline: 1.6033x; 1.6033x over previous
#include <cuda_runtime.h>
#include <cuda_bf16.h>
#include <cstdint>

// Problem constants
#define NN 100000
#define EE 1600000
#define FIN 256
#define FOUT 128      // H*D = 4*32
#define SCAN_CHUNK 256
#define NBLK_SCAN ((NN + SCAN_CHUNK - 1) / SCAN_CHUNK)   // 391

// ---------------- device scratch (static globals; no allocation) -------------
__device__ float4 g_ft4[(size_t)NN * 32];   // ft [N,128] (51.2MB)
__device__ float4 g_el[NN];                 // el [N,4]  (written as float2 halves)
__device__ float4 g_er[NN];                 // er [N,4]
__device__ int    g_cnt[NN];
__device__ int    g_off[NN];
__device__ int    g_cur[NN];
__device__ int    g_srcs[EE];               // src ids sorted by dst
__device__ int    g_part[512];

// ---------------- zero counts ------------------------------------------------
__global__ void k_zero_cnt() {
    int i = blockIdx.x * blockDim.x + threadIdx.x;
    if (i < NN) g_cnt[i] = 0;
}

// ============ bf16x3 split GEMM via mma.sync (sm_80+ path) ===================
// C[128 rows x 128 cols] per block; 8 warps in 4(m) x 2(n); 256 threads.
// K chunked by 32. Split fp32 -> (hi bf16, lo bf16); acc = Ah*Bh + Al*Bh + Ah*Bl.

__device__ __forceinline__ uint32_t pack_bf16x2(float x, float y) {
    __nv_bfloat162 v = __floats2bfloat162_rn(x, y);  // .x -> low 16 bits
    return *reinterpret_cast<uint32_t*>(&v);
}

__device__ __forceinline__ void mma16816(float* c, const uint32_t* a, const uint32_t* b) {
    asm volatile(
        "mma.sync.aligned.m16n8k16.row.col.f32.bf16.bf16.f32 "
        "{%0,%1,%2,%3}, {%4,%5,%6,%7}, {%8,%9}, {%0,%1,%2,%3};"
        : "+f"(c[0]), "+f"(c[1]), "+f"(c[2]), "+f"(c[3])
        : "r"(a[0]), "r"(a[1]), "r"(a[2]), "r"(a[3]), "r"(b[0]), "r"(b[1]));
}

#define SMS 20   // smem row stride in uints (16 used + 4 pad -> conflict-free)

__global__ __launch_bounds__(256, 2)
void k_gemm_mma(const float* __restrict__ A, const float* __restrict__ W,
                const float* __restrict__ al, const float* __restrict__ ar) {
    __shared__ uint32_t sAhi[128 * SMS];
    __shared__ uint32_t sAlo[128 * SMS];
    __shared__ uint32_t sBhi[128 * SMS];
    __shared__ uint32_t sBlo[128 * SMS];

    const int tid = threadIdx.x;
    const int wid = tid >> 5;
    const int lane = tid & 31;
    const int warp_m = wid >> 1;        // 0..3  (32 rows each)
    const int warp_n = wid & 1;         // 0..1  (64 cols each)
    const int row0 = blockIdx.x * 128;
    const int qr = lane >> 2;           // 0..7
    const int qc = lane & 3;            // 0..3

    float acc[2][8][4];
#pragma unroll
    for (int mt = 0; mt < 2; mt++)
#pragma unroll
        for (int nt = 0; nt < 8; nt++)
#pragma unroll
            for (int i = 0; i < 4; i++) acc[mt][nt][i] = 0.f;

    for (int kc = 0; kc < 8; kc++) {
        const int k0 = kc * 32;
        // ---- load + split A chunk (128 x 32 f32 = 1024 float4) ----
#pragma unroll
        for (int t = 0; t < 4; t++) {
            int f = tid + t * 256;
            int row = f >> 3, q = f & 7;
            int grow = row0 + row;
            float4 v = make_float4(0.f, 0.f, 0.f, 0.f);
            if (grow < NN) v = *(const float4*)(A + (size_t)grow * FIN + k0 + q * 4);
            float hx = __bfloat162float(__float2bfloat16(v.x));
            float hy = __bfloat162float(__float2bfloat16(v.y));
            float hz = __bfloat162float(__float2bfloat16(v.z));
            float hw = __bfloat162float(__float2bfloat16(v.w));
            sAhi[row * SMS + q * 2]     = pack_bf16x2(hx, hy);
            sAhi[row * SMS + q * 2 + 1] = pack_bf16x2(hz, hw);
            sAlo[row * SMS + q * 2]     = pack_bf16x2(v.x - hx, v.y - hy);
            sAlo[row * SMS + q * 2 + 1] = pack_bf16x2(v.z - hz, v.w - hw);
        }
        // ---- load + split B chunk (W[128][256], rows = out cols) ----
#pragma unroll
        for (int t = 0; t < 4; t++) {
            int f = tid + t * 256;
            int row = f >> 3, q = f & 7;
            float4 v = *(const float4*)(W + (size_t)row * FIN + k0 + q * 4);
            float hx = __bfloat162float(__float2bfloat16(v.x));
            float hy = __bfloat162float(__float2bfloat16(v.y));
            float hz = __bfloat162float(__float2bfloat16(v.z));
            float hw = __bfloat162float(__float2bfloat16(v.w));
            sBhi[row * SMS + q * 2]     = pack_bf16x2(hx, hy);
            sBhi[row * SMS + q * 2 + 1] = pack_bf16x2(hz, hw);
            sBlo[row * SMS + q * 2]     = pack_bf16x2(v.x - hx, v.y - hy);
            sBlo[row * SMS + q * 2 + 1] = pack_bf16x2(v.z - hz, v.w - hw);
        }
        __syncthreads();

        // ---- MMA phase: 2 k16-steps per chunk ----
#pragma unroll
        for (int ks = 0; ks < 2; ks++) {
            const int ku = ks * 8;  // uint col base
            uint32_t ah[2][4], alo_[2][4], b[8][2];
#pragma unroll
            for (int mt = 0; mt < 2; mt++) {
                int r = (warp_m * 32 + mt * 16 + qr) * SMS + ku + qc;
                ah[mt][0] = sAhi[r];            ah[mt][1] = sAhi[r + 8 * SMS];
                ah[mt][2] = sAhi[r + 4];        ah[mt][3] = sAhi[r + 8 * SMS + 4];
                alo_[mt][0] = sAlo[r];          alo_[mt][1] = sAlo[r + 8 * SMS];
                alo_[mt][2] = sAlo[r + 4];      alo_[mt][3] = sAlo[r + 8 * SMS + 4];
            }
            // Bhi: Ah*Bh and Al*Bh
#pragma unroll
            for (int nt = 0; nt < 8; nt++) {
                int rb = (warp_n * 64 + nt * 8 + qr) * SMS + ku + qc;
                b[nt][0] = sBhi[rb]; b[nt][1] = sBhi[rb + 4];
            }
#pragma unroll
            for (int mt = 0; mt < 2; mt++)
#pragma unroll
                for (int nt = 0; nt < 8; nt++) mma16816(acc[mt][nt], ah[mt], b[nt]);
#pragma unroll
            for (int mt = 0; mt < 2; mt++)
#pragma unroll
                for (int nt = 0; nt < 8; nt++) mma16816(acc[mt][nt], alo_[mt], b[nt]);
            // Blo: Ah*Bl
#pragma unroll
            for (int nt = 0; nt < 8; nt++) {
                int rb = (warp_n * 64 + nt * 8 + qr) * SMS + ku + qc;
                b[nt][0] = sBlo[rb]; b[nt][1] = sBlo[rb + 4];
            }
#pragma unroll
            for (int mt = 0; mt < 2; mt++)
#pragma unroll
                for (int nt = 0; nt < 8; nt++) mma16816(acc[mt][nt], ah[mt], b[nt]);
        }
        __syncthreads();
    }

    // ---- epilogue: store ft + fused el/er ----
    float* ft = (float*)g_ft4;
    float2* el2 = (float2*)g_el;
    float2* er2 = (float2*)g_er;

#pragma unroll
    for (int mt = 0; mt < 2; mt++) {
        int r0 = row0 + warp_m * 32 + mt * 16 + qr;   // rows r0 and r0+8
        int r1 = r0 + 8;
        // per-thread partial el/er for the warp's two heads, both row-halves
        float el_lo[2] = {0.f, 0.f}, el_hi[2] = {0.f, 0.f};
        float er_lo[2] = {0.f, 0.f}, er_hi[2] = {0.f, 0.f};
#pragma unroll
        for (int nt = 0; nt < 8; nt++) {
            int c = warp_n * 64 + nt * 8 + qc * 2;
            int h = nt >> 2;  // local head (0 or 1)
            float al0 = __ldg(al + c), al1 = __ldg(al + c + 1);
            float ar0 = __ldg(ar + c), ar1 = __ldg(ar + c + 1);
            el_lo[h] += acc[mt][nt][0] * al0 + acc[mt][nt][1] * al1;
            er_lo[h] += acc[mt][nt][0] * ar0 + acc[mt][nt][1] * ar1;
            el_hi[h] += acc[mt][nt][2] * al0 + acc[mt][nt][3] * al1;
            er_hi[h] += acc[mt][nt][2] * ar0 + acc[mt][nt][3] * ar1;
            // store ft (32B contiguous per lane quad -> full sectors)
            if (r0 < NN)
                *(float2*)(ft + (size_t)r0 * FOUT + c) = make_float2(acc[mt][nt][0], acc[mt][nt][1]);
            if (r1 < NN)
                *(float2*)(ft + (size_t)r1 * FOUT + c) = make_float2(acc[mt][nt][2], acc[mt][nt][3]);
        }
        // reduce across the lane quad (lanes sharing a row)
#pragma unroll
        for (int h = 0; h < 2; h++) {
#pragma unroll
            for (int o = 1; o <= 2; o <<= 1) {
                el_lo[h] += __shfl_xor_sync(0xFFFFFFFFu, el_lo[h], o);
                el_hi[h] += __shfl_xor_sync(0xFFFFFFFFu, el_hi[h], o);
                er_lo[h] += __shfl_xor_sync(0xFFFFFFFFu, er_lo[h], o);
                er_hi[h] += __shfl_xor_sync(0xFFFFFFFFu, er_hi[h], o);
            }
        }
        if (qc == 0) {
            if (r0 < NN) {
                el2[(size_t)r0 * 2 + warp_n] = make_float2(el_lo[0], el_lo[1]);
                er2[(size_t)r0 * 2 + warp_n] = make_float2(er_lo[0], er_lo[1]);
            }
            if (r1 < NN) {
                el2[(size_t)r1 * 2 + warp_n] = make_float2(el_hi[0], el_hi[1]);
                er2[(size_t)r1 * 2 + warp_n] = make_float2(er_hi[0], er_hi[1]);
            }
        }
    }
}

// ---------------- degree histogram -------------------------------------------
__global__ void k_hist(const int* __restrict__ dst) {
    int e = blockIdx.x * blockDim.x + threadIdx.x;
    if (e < EE) atomicAdd(&g_cnt[dst[e]], 1);
}

// ---------------- scan: block sums -------------------------------------------
__global__ void k_blocksum() {
    __shared__ int s[SCAN_CHUNK];
    int t = threadIdx.x;
    int i = blockIdx.x * SCAN_CHUNK + t;
    s[t] = (i < NN) ? g_cnt[i] : 0;
    __syncthreads();
#pragma unroll
    for (int o = SCAN_CHUNK / 2; o > 0; o >>= 1) {
        if (t < o) s[t] += s[t + o];
        __syncthreads();
    }
    if (t == 0) g_part[blockIdx.x] = s[0];
}

// ---------------- scan: exclusive scan of partials (one block) ---------------
__global__ void k_scanpart() {
    __shared__ int s[512];
    int t = threadIdx.x;
    s[t] = (t < NBLK_SCAN) ? g_part[t] : 0;
    __syncthreads();
    for (int o = 1; o < 512; o <<= 1) {
        int add = (t >= o) ? s[t - o] : 0;
        __syncthreads();
        s[t] += add;
        __syncthreads();
    }
    if (t < NBLK_SCAN) g_part[t] = (t == 0) ? 0 : s[t - 1];
}

// ---------------- scan: write offsets + cursors ------------------------------
__global__ void k_scanwrite() {
    __shared__ int s[SCAN_CHUNK];
    int t = threadIdx.x;
    int i = blockIdx.x * SCAN_CHUNK + t;
    s[t] = (i < NN) ? g_cnt[i] : 0;
    __syncthreads();
    for (int o = 1; o < SCAN_CHUNK; o <<= 1) {
        int add = (t >= o) ? s[t - o] : 0;
        __syncthreads();
        s[t] += add;
        __syncthreads();
    }
    int excl = (t == 0) ? 0 : s[t - 1];
    int base = g_part[blockIdx.x];
    if (i < NN) {
        g_off[i] = base + excl;
        g_cur[i] = base + excl;
    }
}

// ---------------- scatter edges by dst ---------------------------------------
__global__ void k_scatter(const int* __restrict__ src, const int* __restrict__ dst) {
    int e = blockIdx.x * blockDim.x + threadIdx.x;
    if (e >= EE) return;
    int d = dst[e];
    int pos = atomicAdd(&g_cur[d], 1);
    g_srcs[pos] = src[e];
}

// ---------------- aggregation: warp per dst node -----------------------------
__global__ void k_agg(float* __restrict__ out) {
    int gw = (blockIdx.x * blockDim.x + threadIdx.x) >> 5;
    int lane = threadIdx.x & 31;
    if (gw >= NN) return;

    const int start = g_off[gw];
    const int cnt = g_cnt[gw];
    const float4 er4 = g_er[gw];
    const float* ft = (const float*)g_ft4;

    float s0 = 0.f, s1 = 0.f, s2 = 0.f, s3 = 0.f;
    float a0 = 0.f, a1 = 0.f, a2 = 0.f, a3 = 0.f;

    for (int i = 0; i < cnt; i++) {
        int s = g_srcs[start + i];
        float4 el4 = g_el[s];
        float e0 = el4.x + er4.x; e0 = (e0 > 0.f) ? e0 : 0.2f * e0;
        float e1 = el4.y + er4.y; e1 = (e1 > 0.f) ? e1 : 0.2f * e1;
        float e2 = el4.z + er4.z; e2 = (e2 > 0.f) ? e2 : 0.2f * e2;
        float e3 = el4.w + er4.w; e3 = (e3 > 0.f) ? e3 : 0.2f * e3;
        float p0 = __expf(e0), p1 = __expf(e1), p2 = __expf(e2), p3 = __expf(e3);
        const float* fs = ft + (size_t)s * FOUT + lane;
        a0 = fmaf(p0, fs[0],  a0);
        a1 = fmaf(p1, fs[32], a1);
        a2 = fmaf(p2, fs[64], a2);
        a3 = fmaf(p3, fs[96], a3);
        s0 += p0; s1 += p1; s2 += p2; s3 += p3;
    }

    float* o = out + (size_t)gw * FOUT + lane;
    o[0]  = (s0 > 0.f) ? a0 / s0 : 0.f;
    o[32] = (s1 > 0.f) ? a1 / s1 : 0.f;
    o[64] = (s2 > 0.f) ? a2 / s2 : 0.f;
    o[96] = (s3 > 0.f) ? a3 / s3 : 0.f;
}

// ---------------- launch ------------------------------------------------------
extern "C" void kernel_launch(void* const* d_in, const int* in_sizes, int n_in,
                              void* d_out, int out_size) {
    const float* feat = (const float*)d_in[0];
    const float* fc_w = (const float*)d_in[1];
    const float* attn_l = (const float*)d_in[2];
    const float* attn_r = (const float*)d_in[3];
    const int* src = (const int*)d_in[4];
    const int* dst = (const int*)d_in[5];
    float* out = (float*)d_out;

    (void)in_sizes; (void)n_in; (void)out_size;

    k_zero_cnt<<<(NN + 511) / 512, 512>>>();
    k_gemm_mma<<<(NN + 127) / 128, 256>>>(feat, fc_w, attn_l, attn_r);
    k_hist<<<(EE + 255) / 256, 256>>>(dst);
    k_blocksum<<<NBLK_SCAN, SCAN_CHUNK>>>();
    k_scanpart<<<1, 512>>>();
    k_scanwrite<<<NBLK_SCAN, SCAN_CHUNK>>>();
    k_scatter<<<(EE + 255) / 256, 256>>>(src, dst);
    k_agg<<<(NN * 32 + 255) / 256, 256>>>(out);
}